// round 1
// baseline (speedup 1.0000x reference)
#include <cuda_runtime.h>
#include <cstddef>

#define T_DIM    2048
#define B_DIM    16
#define I_DIM    512
#define H_DIM    512
#define W_STRIDE 1024           // weight row stride = I + H
#define N_CHUNK  128
#define L_CHUNK  16             // N_CHUNK * L_CHUNK == T_DIM

// ---------------- device scratch (static: no allocations allowed) ----------------
__device__ float g_P[2][H_DIM * H_DIM];                 // ping-pong for M^L squaring
__device__ float g_local_end[N_CHUNK][B_DIM * H_DIM];   // chunk-local end states
__device__ float g_hstart[N_CHUNK][B_DIM * H_DIM];      // corrected chunk start states

// =================================================================================
// Kernel 1: x_proj GEMM.  out[m][n] = sum_k A[m][k] * W[n][512+k] + bias[n]
// A = inputs flattened (M = T*B rows, K = 512 contiguous), W rows are K-contiguous.
// 64x64 tile, BK=16, 256 threads, 4x4 microtile.
// =================================================================================
__global__ __launch_bounds__(256) void xproj_gemm(const float* __restrict__ A,
                                                  const float* __restrict__ W,
                                                  const float* __restrict__ bias,
                                                  float* __restrict__ out) {
    __shared__ __align__(16) float As[16][64];
    __shared__ __align__(16) float Bs[16][64];
    const int m0 = blockIdx.y * 64;
    const int n0 = blockIdx.x * 64;
    const int tid = threadIdx.x;
    const int lr = tid >> 2;          // 0..63
    const int lk = (tid & 3) << 2;    // 0,4,8,12
    const int ty = tid >> 4;          // 0..15
    const int tx = tid & 15;          // 0..15

    float acc[4][4];
#pragma unroll
    for (int i = 0; i < 4; i++)
#pragma unroll
        for (int j = 0; j < 4; j++) acc[i][j] = 0.f;

    for (int kt = 0; kt < I_DIM; kt += 16) {
        float4 va = *(const float4*)(A + (size_t)(m0 + lr) * I_DIM + kt + lk);
        float4 vb = *(const float4*)(W + (size_t)(n0 + lr) * W_STRIDE + H_DIM + kt + lk);
        As[lk + 0][lr] = va.x; As[lk + 1][lr] = va.y;
        As[lk + 2][lr] = va.z; As[lk + 3][lr] = va.w;
        Bs[lk + 0][lr] = vb.x; Bs[lk + 1][lr] = vb.y;
        Bs[lk + 2][lr] = vb.z; Bs[lk + 3][lr] = vb.w;
        __syncthreads();
#pragma unroll
        for (int k = 0; k < 16; k++) {
            float4 a4 = *(const float4*)&As[k][ty << 2];
            float4 b4 = *(const float4*)&Bs[k][tx << 2];
            float av[4] = {a4.x, a4.y, a4.z, a4.w};
            float bv[4] = {b4.x, b4.y, b4.z, b4.w};
#pragma unroll
            for (int i = 0; i < 4; i++)
#pragma unroll
                for (int j = 0; j < 4; j++) acc[i][j] += av[i] * bv[j];
        }
        __syncthreads();
    }
#pragma unroll
    for (int i = 0; i < 4; i++) {
        int m = m0 + (ty << 2) + i;
        int n = n0 + (tx << 2);
        float4 r;
        r.x = acc[i][0] + bias[n + 0];
        r.y = acc[i][1] + bias[n + 1];
        r.z = acc[i][2] + bias[n + 2];
        r.w = acc[i][3] + bias[n + 3];
        *(float4*)(out + (size_t)m * H_DIM + n) = r;
    }
}

// =================================================================================
// Kernel 2: init P0[k][j] = w_hh[j][k]  (the right-multiplier M with h_new = h @ M)
// =================================================================================
__global__ void init_P(const float* __restrict__ W) {
    int k = blockIdx.x;
    int j = threadIdx.x;
    g_P[0][k * H_DIM + j] = W[(size_t)j * W_STRIDE + k];
}

// =================================================================================
// Kernel 3: square a 512x512 matrix (row-major): g_P[dst] = g_P[src] * g_P[src]
// =================================================================================
__global__ __launch_bounds__(256) void mm_square(int src, int dst) {
    const float* A = g_P[src];
    const float* B = g_P[src];
    float* C = g_P[dst];
    __shared__ __align__(16) float As[16][64];
    __shared__ __align__(16) float Bs[16][64];
    const int m0 = blockIdx.y * 64;
    const int n0 = blockIdx.x * 64;
    const int tid = threadIdx.x;
    const int lr = tid >> 2;
    const int lk = (tid & 3) << 2;
    const int kr = tid >> 4;          // 0..15
    const int nq = (tid & 15) << 2;   // 0..60
    const int ty = tid >> 4;
    const int tx = tid & 15;

    float acc[4][4];
#pragma unroll
    for (int i = 0; i < 4; i++)
#pragma unroll
        for (int j = 0; j < 4; j++) acc[i][j] = 0.f;

    for (int kt = 0; kt < H_DIM; kt += 16) {
        float4 va = *(const float4*)(A + (size_t)(m0 + lr) * H_DIM + kt + lk);
        As[lk + 0][lr] = va.x; As[lk + 1][lr] = va.y;
        As[lk + 2][lr] = va.z; As[lk + 3][lr] = va.w;
        float4 vb = *(const float4*)(B + (size_t)(kt + kr) * H_DIM + n0 + nq);
        *(float4*)&Bs[kr][nq] = vb;
        __syncthreads();
#pragma unroll
        for (int k = 0; k < 16; k++) {
            float4 a4 = *(const float4*)&As[k][ty << 2];
            float4 b4 = *(const float4*)&Bs[k][tx << 2];
            float av[4] = {a4.x, a4.y, a4.z, a4.w};
            float bv[4] = {b4.x, b4.y, b4.z, b4.w};
#pragma unroll
            for (int i = 0; i < 4; i++)
#pragma unroll
                for (int j = 0; j < 4; j++) acc[i][j] += av[i] * bv[j];
        }
        __syncthreads();
    }
#pragma unroll
    for (int i = 0; i < 4; i++) {
        int m = m0 + (ty << 2) + i;
        int n = n0 + (tx << 2);
        float4 r = {acc[i][0], acc[i][1], acc[i][2], acc[i][3]};
        *(float4*)(C + (size_t)m * H_DIM + n) = r;
    }
}

// =================================================================================
// Kernel 4/6: chunk-local scan.  One CTA per chunk.  h kept in SMEM (16x512 fp32).
// Each step: h_new[b][j] = sum_k h[b][k]*w_hh[j][k] + xp[t][b][j].
// Thread owns 2 adjacent j columns for all 16 batches (32 accumulators).
// W rows are streamed from L2 once per step and reused across the 16 batches.
// PASS==1: zero init, store only chunk end state.  PASS==2: init from g_hstart,
// write all outputs (in place over xp) and optionally the final state.
// =================================================================================
template <int PASS>
__global__ __launch_bounds__(256) void scan_pass(const float* __restrict__ xp,
                                                 const float* __restrict__ W,
                                                 float* __restrict__ out,
                                                 float* __restrict__ last) {
    const int c = blockIdx.x;
    const int tid = threadIdx.x;      // 256 threads
    __shared__ __align__(16) float h[B_DIM][H_DIM];   // 32 KB

    if (PASS == 1) {
        for (int i = tid; i < B_DIM * H_DIM; i += 256) ((float*)h)[i] = 0.f;
    } else {
        const float* hs = g_hstart[c];
        for (int i = tid; i < B_DIM * H_DIM; i += 256) ((float*)h)[i] = hs[i];
    }
    __syncthreads();

    const int j0 = tid * 2;
    const float* w0 = W + (size_t)j0 * W_STRIDE;        // w_hh row j0 (k contiguous)
    const float* w1 = w0 + W_STRIDE;                    // w_hh row j0+1

    for (int s = 0; s < L_CHUNK; s++) {
        const int t = c * L_CHUNK + s;
        const float* xpt = xp + (size_t)t * B_DIM * H_DIM;
        float acc0[B_DIM], acc1[B_DIM];
#pragma unroll
        for (int b = 0; b < B_DIM; b++) {
            float2 xv = *(const float2*)(xpt + b * H_DIM + j0);
            acc0[b] = xv.x;
            acc1[b] = xv.y;
        }
#pragma unroll 2
        for (int k = 0; k < H_DIM; k += 4) {
            float4 wa = *(const float4*)(w0 + k);
            float4 wb = *(const float4*)(w1 + k);
#pragma unroll
            for (int b = 0; b < B_DIM; b++) {
                float4 hv = *(const float4*)&h[b][k];
                acc0[b] += hv.x * wa.x + hv.y * wa.y + hv.z * wa.z + hv.w * wa.w;
                acc1[b] += hv.x * wb.x + hv.y * wb.y + hv.z * wb.z + hv.w * wb.w;
            }
        }
        __syncthreads();
#pragma unroll
        for (int b = 0; b < B_DIM; b++) {
            h[b][j0] = acc0[b];
            h[b][j0 + 1] = acc1[b];
        }
        __syncthreads();
        if (PASS == 2) {
            float* ot = out + (size_t)t * B_DIM * H_DIM;
#pragma unroll
            for (int b = 0; b < B_DIM; b++) {
                float2 v = {acc0[b], acc1[b]};
                *(float2*)(ot + b * H_DIM + j0) = v;
            }
        }
    }

    if (PASS == 1) {
        float* le = g_local_end[c];
#pragma unroll
        for (int b = 0; b < B_DIM; b++) {
            le[b * H_DIM + j0] = h[b][j0];
            le[b * H_DIM + j0 + 1] = h[b][j0 + 1];
        }
    } else if (c == N_CHUNK - 1 && last != nullptr) {
        for (int i = tid; i < B_DIM * H_DIM; i += 256) last[i] = ((float*)h)[i];
    }
}

// =================================================================================
// Kernel 5: boundary scan across chunks.  One CTA per batch row b.
// hstart[0] = state;  hstart[c+1] = hstart[c] @ P + local_end[c],  P = M^L in g_P[0].
// 256 threads: lower 128 own 4 j-columns over k in [0,256), upper 128 over [256,512);
// partial sums reduced through SMEM.
// =================================================================================
__global__ __launch_bounds__(256) void boundary_scan(const float* __restrict__ state) {
    const int b = blockIdx.x;
    const int tid = threadIdx.x;
    __shared__ __align__(16) float h[H_DIM];
    __shared__ __align__(16) float part[H_DIM];

    for (int i = tid; i < H_DIM; i += 256) h[i] = state[(size_t)b * H_DIM + i];
    __syncthreads();

    const float* P = g_P[0];
    const int jq = (tid & 127) * 4;
    const int kh = tid >> 7;           // 0 or 1
    const int kbeg = kh * 256;

    for (int c = 0; c < N_CHUNK; c++) {
        // publish incoming state of chunk c
        g_hstart[c][(size_t)b * H_DIM + 2 * tid]     = h[2 * tid];
        g_hstart[c][(size_t)b * H_DIM + 2 * tid + 1] = h[2 * tid + 1];

        float4 acc = {0.f, 0.f, 0.f, 0.f};
#pragma unroll 4
        for (int k = kbeg; k < kbeg + 256; k++) {
            float hk = h[k];
            float4 p = *(const float4*)(P + (size_t)k * H_DIM + jq);
            acc.x += hk * p.x; acc.y += hk * p.y;
            acc.z += hk * p.z; acc.w += hk * p.w;
        }
        __syncthreads();                     // all reads of h done
        if (kh) *(float4*)&part[jq] = acc;
        __syncthreads();
        if (!kh) {
            float4 pr = *(const float4*)&part[jq];
            float4 le = *(const float4*)(g_local_end[c] + (size_t)b * H_DIM + jq);
            acc.x += pr.x + le.x; acc.y += pr.y + le.y;
            acc.z += pr.z + le.z; acc.w += pr.w + le.w;
            *(float4*)&h[jq] = acc;
        }
        __syncthreads();
    }
}

// =================================================================================
// kernel_launch
// =================================================================================
extern "C" void kernel_launch(void* const* d_in, const int* in_sizes, int n_in,
                              void* d_out, int out_size) {
    const float* inp = nullptr;
    const float* state = nullptr;
    const float* weight = nullptr;
    const float* bias = nullptr;
    for (int i = 0; i < n_in; i++) {
        switch (in_sizes[i]) {
            case T_DIM * B_DIM * I_DIM: inp = (const float*)d_in[i]; break;
            case B_DIM * H_DIM:         state = (const float*)d_in[i]; break;
            case H_DIM * W_STRIDE:      weight = (const float*)d_in[i]; break;
            case H_DIM:                 bias = (const float*)d_in[i]; break;
            default: break;
        }
    }
    float* out = (float*)d_out;
    float* last = (out_size >= T_DIM * B_DIM * H_DIM + B_DIM * H_DIM)
                      ? out + (size_t)T_DIM * B_DIM * H_DIM
                      : nullptr;

    // 1. x_proj into the outputs region (used as xp scratch, overwritten by pass 2)
    xproj_gemm<<<dim3(H_DIM / 64, (T_DIM * B_DIM) / 64), 256>>>(inp, weight, bias, out);

    // 2. P = M = w_hh^T, then square log2(L)=4 times -> M^16 in g_P[0]
    init_P<<<H_DIM, H_DIM>>>(weight);
    mm_square<<<dim3(8, 8), 256>>>(0, 1);   // M^2
    mm_square<<<dim3(8, 8), 256>>>(1, 0);   // M^4
    mm_square<<<dim3(8, 8), 256>>>(0, 1);   // M^8
    mm_square<<<dim3(8, 8), 256>>>(1, 0);   // M^16

    // 3. chunk-local scans (zero init) -> local end states
    scan_pass<1><<<N_CHUNK, 256>>>(out, weight, nullptr, nullptr);

    // 4. boundary scan -> corrected chunk start states
    boundary_scan<<<B_DIM, 256>>>(state);

    // 5. final scans with correct initial states, write outputs (+ last state)
    scan_pass<2><<<N_CHUNK, 256>>>(out, weight, out, last);
}